// round 15
// baseline (speedup 1.0000x reference)
#include <cuda_runtime.h>
#include <cuda_fp16.h>
#include <cstdint>

#define D_MODEL 1024
#define NHEADS  16
#define HDIM    64
#define BATCH   2
#define SEQ     2048
#define NROWS   (BATCH * SEQ)   // 4096
#define QTILE   128

// 0.125 * log2(e): folded into Wq so attention scores are in log2 units pre-scaled
#define QSCALE 0.18033688011112042f

// ---------------- scratch (static device globals; no allocations) ----------------
__device__ __half g_Qh[BATCH * NHEADS * SEQ * HDIM];   // [B,H,S,Dh] fp16
__device__ __half g_Kh[BATCH * NHEADS * SEQ * HDIM];
__device__ __half g_Vh[BATCH * NHEADS * SEQ * HDIM];
__device__ __half g_Xh[NROWS * D_MODEL];               // fp16: x, then ctx
__device__ __half g_Wh[4 * D_MODEL * D_MODEL];         // fp16 W [z][k][n] (Wq pre-scaled)

// ---------------- ptx helpers (sm_80-class only; NO tcgen05 on this target) ------
__device__ __forceinline__ void cp16(uint32_t smem, const void* gmem) {
    asm volatile("cp.async.cg.shared.global [%0], [%1], 16;" :: "r"(smem), "l"(gmem));
}
#define CP_COMMIT() asm volatile("cp.async.commit_group;" ::: "memory")
template <int N>
__device__ __forceinline__ void cp_wait() {
    asm volatile("cp.async.wait_group %0;" :: "n"(N) : "memory");
}
__device__ __forceinline__ float ex2(float x) {
    float y;
    asm("ex2.approx.f32 %0, %1;" : "=f"(y) : "f"(x));
    return y;
}
__device__ __forceinline__ void ldmatrix_x4(uint32_t& r0, uint32_t& r1,
                                            uint32_t& r2, uint32_t& r3, uint32_t addr) {
    asm volatile("ldmatrix.sync.aligned.m8n8.x4.shared.b16 {%0,%1,%2,%3}, [%4];"
                 : "=r"(r0), "=r"(r1), "=r"(r2), "=r"(r3) : "r"(addr));
}
__device__ __forceinline__ void ldmatrix_x4_trans(uint32_t& r0, uint32_t& r1,
                                                  uint32_t& r2, uint32_t& r3, uint32_t addr) {
    asm volatile("ldmatrix.sync.aligned.m8n8.x4.trans.shared.b16 {%0,%1,%2,%3}, [%4];"
                 : "=r"(r0), "=r"(r1), "=r"(r2), "=r"(r3) : "r"(addr));
}
__device__ __forceinline__ void mma_f16(float* c,
    uint32_t a0, uint32_t a1, uint32_t a2, uint32_t a3, uint32_t b0, uint32_t b1)
{
    asm volatile(
        "mma.sync.aligned.m16n8k16.row.col.f32.f16.f16.f32 "
        "{%0,%1,%2,%3}, {%4,%5,%6,%7}, {%8,%9}, {%0,%1,%2,%3};\n"
        : "+f"(c[0]), "+f"(c[1]), "+f"(c[2]), "+f"(c[3])
        : "r"(a0), "r"(a1), "r"(a2), "r"(a3), "r"(b0), "r"(b1));
}
__device__ __forceinline__ uint32_t pack_f16(float x0, float x1) {
    __half2 h = __floats2half2_rn(x0, x1);
    return *(uint32_t*)&h;
}

// =================================================================================
// Pre-pass: fp16 conversions. Wq is pre-scaled by QSCALE (attention scale fold).
// =================================================================================
__global__ __launch_bounds__(256) void conv_x_kernel(const float* __restrict__ src)
{
    const size_t i = ((size_t)blockIdx.x * 256 + threadIdx.x) * 4;
    float4 v = *(const float4*)(src + i);
    __half2 p0 = __floats2half2_rn(v.x, v.y);
    __half2 p1 = __floats2half2_rn(v.z, v.w);
    *(uint2*)(g_Xh + i) = make_uint2(*(uint32_t*)&p0, *(uint32_t*)&p1);
}
__global__ __launch_bounds__(256) void conv_w_kernel(
    const float* __restrict__ W0, const float* __restrict__ W1,
    const float* __restrict__ W2, const float* __restrict__ W3)
{
    const float* W = (blockIdx.z == 0) ? W0 : (blockIdx.z == 1) ? W1
                   : (blockIdx.z == 2) ? W2 : W3;
    const float s = (blockIdx.z == 0) ? QSCALE : 1.0f;
    const size_t o = (size_t)blockIdx.z * D_MODEL * D_MODEL;
    const size_t i = ((size_t)blockIdx.x * 256 + threadIdx.x) * 4;
    float4 v = *(const float4*)(W + i);
    __half2 p0 = __floats2half2_rn(v.x * s, v.y * s);
    __half2 p1 = __floats2half2_rn(v.z * s, v.w * s);
    *(uint2*)(g_Wh + o + i) = make_uint2(*(uint32_t*)&p0, *(uint32_t*)&p1);
}

// =================================================================================
// fp16 1-pass GEMM: cp.async double-buffered, BK=32, block 256x128, 512 threads =
// 16 warps (4x4), warp tile 64x32 (fragment code identical to verified Round-13).
// A smem [m][k] pitch 80B; B smem [k][n] pitch 272B. m-tile 256 halves W L2 traffic.
// QKV=1: A=g_Xh(x), B=g_Wh[z], out -> fp16 g_Qh/g_Kh/g_Vh [B,H,S,Dh].
// QKV=0: A=g_Xh(ctx), B=g_Wh[3](Wo), out -> fp32 row-major Cout.
// =================================================================================
#define STG_A 0
#define STG_B 20480
#define STG_SZ 29184
#define GSMEM (2 * STG_SZ)   // 58368

template <int QKV>
__global__ __launch_bounds__(512, 1) void f16_gemm(float* __restrict__ Cout)
{
    extern __shared__ uint8_t smem[];
    const uint32_t sb = (uint32_t)__cvta_generic_to_shared(smem);
    const int t = threadIdx.x, lane = t & 31, wid = t >> 5;
    const int g = lane >> 2, tq = lane & 3, quad = lane >> 3, idx8 = lane & 7;
    const int wm = (wid & 3) * 64;        // 4 m-warps over 256 rows
    const int wn = (wid >> 2) * 32;       // 4 n-warps over 128 cols
    const int m0 = blockIdx.y * 256, n0 = blockIdx.x * 128;
    const int z  = QKV ? (int)blockIdx.z : 3;

    const __half* A  = g_Xh;
    const __half* Wp = g_Wh + (size_t)z * D_MODEL * D_MODEL;

    float acc[4][4][4];
#pragma unroll
    for (int mf = 0; mf < 4; mf++)
#pragma unroll
        for (int nf = 0; nf < 4; nf++)
#pragma unroll
            for (int r = 0; r < 4; r++) acc[mf][nf][r] = 0.0f;

    auto load_stage = [&](int buf, int ks) {
        const uint32_t base = sb + buf * STG_SZ;
        // A: 256 rows x 64B = 1024 chunks; 2 per thread
#pragma unroll
        for (int half = 0; half < 2; half++) {
            const int c   = t + half * 512;
            const int row = c >> 2;
            cp16(base + STG_A + row * 80 + (c & 3) * 16,
                 A + (size_t)(m0 + row) * D_MODEL + ks + (c & 3) * 8);
        }
        // B: 32 k-rows x 256B = 512 chunks; 1 per thread
        {
            const int row = t >> 4;
            cp16(base + STG_B + row * 272 + (t & 15) * 16,
                 Wp + (size_t)(ks + row) * D_MODEL + n0 + (t & 15) * 8);
        }
        CP_COMMIT();
    };

    load_stage(0, 0);
    load_stage(1, 32);
    int ks = 64;

    constexpr int NIT = D_MODEL / 32;   // 32
    for (int it = 0; it < NIT; ++it) {
        if (it + 1 < NIT) cp_wait<1>(); else cp_wait<0>();
        __syncthreads();

        const uint32_t ab = sb + (it & 1) * STG_SZ;
        const uint32_t aA = ab + STG_A, aB = ab + STG_B;

#pragma unroll
        for (int kb = 0; kb < 2; kb++) {
            uint32_t af[4][4], bf[4][2];
#pragma unroll
            for (int mf = 0; mf < 4; mf++) {
                const uint32_t off =
                    (uint32_t)((wm + mf * 16 + (lane & 15)) * 80 +
                               (kb * 8 + (lane >> 4) * 4) * 4);
                ldmatrix_x4(af[mf][0], af[mf][1], af[mf][2], af[mf][3], aA + off);
            }
#pragma unroll
            for (int np = 0; np < 2; np++) {
                const uint32_t boff =
                    (uint32_t)((kb * 16 + (quad & 1) * 8 + idx8) * 272 +
                               (wn / 2 + np * 8 + (quad >> 1) * 4) * 4);
                uint32_t r0, r1, r2, r3;
                ldmatrix_x4_trans(r0, r1, r2, r3, aB + boff);
                bf[2 * np][0] = r0; bf[2 * np][1] = r1;
                bf[2 * np + 1][0] = r2; bf[2 * np + 1][1] = r3;
            }
#pragma unroll
            for (int mf = 0; mf < 4; mf++)
#pragma unroll
                for (int nf = 0; nf < 4; nf++)
                    mma_f16(acc[mf][nf], af[mf][0], af[mf][1], af[mf][2], af[mf][3],
                            bf[nf][0], bf[nf][1]);
        }
        __syncthreads();
        if (it + 2 < NIT) {
            load_stage(it & 1, ks);
            ks += 32;
        }
    }

    // epilogue (verified layout): c0=(g,2tq) c1=(g,2tq+1) c2=(g+8,2tq) c3=(g+8,2tq+1)
#pragma unroll
    for (int mf = 0; mf < 4; mf++) {
#pragma unroll
        for (int nf = 0; nf < 4; nf++) {
            const int n = n0 + wn + nf * 8 + 2 * tq;
#pragma unroll
            for (int half = 0; half < 2; half++) {
                const int m = m0 + wm + mf * 16 + g + half * 8;
                const float c0 = acc[mf][nf][half * 2 + 0];
                const float c1 = acc[mf][nf][half * 2 + 1];
                if (QKV) {
                    const int b  = m >> 11;
                    const int s  = m & (SEQ - 1);
                    const int h  = n >> 6;
                    const int dd = n & (HDIM - 1);
                    __half2 hv = __floats2half2_rn(c0, c1);
                    __half* dst = (z == 0) ? g_Qh : (z == 1) ? g_Kh : g_Vh;
                    *(__half2*)&dst[(((size_t)(b * NHEADS + h)) * SEQ + s) * HDIM + dd] = hv;
                } else {
                    *(float2*)&Cout[(size_t)m * D_MODEL + n] = make_float2(c0, c1);
                }
            }
        }
    }
}

// =================================================================================
// fp16 tensor-core causal flash attention, KV tile = 128 rows per barrier phase
// (two verified 64-col compute chunks back-to-back). Scores in log2 units (Wq
// pre-scaled), exp = EX2. Epilogue writes ctx fp16 into g_Xh.
// =================================================================================
__global__ __launch_bounds__(256, 2) void attn_mma_kernel()
{
    constexpr int KP = 36;
    __shared__ __align__(16) uint32_t Ks[128 * KP];
    __shared__ __align__(16) uint32_t Vs[128 * KP];

    const int t    = threadIdx.x;
    const int lane = t & 31;
    const int wid  = t >> 5;
    const int g    = lane >> 2;
    const int tq   = lane & 3;
    const int quad = lane >> 3;
    const int idx8 = lane & 7;

    const int qt = (int)gridDim.x - 1 - (int)blockIdx.x;   // heavy first
    const int h  = blockIdx.y;
    const int b  = blockIdx.z;
    const int bh = b * NHEADS + h;
    const __half* Qb = g_Qh + (size_t)bh * SEQ * HDIM;
    const __half* Kb = g_Kh + (size_t)bh * SEQ * HDIM;
    const __half* Vb = g_Vh + (size_t)bh * SEQ * HDIM;
    const int q0  = qt * QTILE;
    const int wr0 = q0 + wid * 16;

    uint32_t qa[4][4];
#pragma unroll
    for (int kb = 0; kb < 4; kb++) {
        const int col = kb * 16 + 2 * tq;
        qa[kb][0] = *(const uint32_t*)&Qb[(size_t)(wr0 + g) * HDIM + col];
        qa[kb][1] = *(const uint32_t*)&Qb[(size_t)(wr0 + g + 8) * HDIM + col];
        qa[kb][2] = *(const uint32_t*)&Qb[(size_t)(wr0 + g) * HDIM + col + 8];
        qa[kb][3] = *(const uint32_t*)&Qb[(size_t)(wr0 + g + 8) * HDIM + col + 8];
    }

    float m0 = -1e30f, m1 = -1e30f, l0 = 0.0f, l1 = 0.0f;
    float o[8][4];
#pragma unroll
    for (int nf = 0; nf < 8; nf++)
#pragma unroll
        for (int r = 0; r < 4; r++) o[nf][r] = 0.0f;

    const uint32_t ks_base = (uint32_t)__cvta_generic_to_shared(Ks);
    const uint32_t vs_base = (uint32_t)__cvta_generic_to_shared(Vs);

    const int lr = t >> 2;
    const int lc = (t & 3) * 4;

    const int njt = (q0 + QTILE) / 128;   // qt + 1 phases of 128 KV rows
    for (int jt = 0; jt < njt; jt++) {
        __syncthreads();
        const __half* Kt = Kb + (size_t)jt * 128 * HDIM;
        const __half* Vt = Vb + (size_t)jt * 128 * HDIM;
#pragma unroll
        for (int half = 0; half < 2; half++) {
            const int r = lr + half * 64;
            *(uint4*)&Ks[r * KP + lc]      = *(const uint4*)&Kt[r * HDIM + lc * 2];
            *(uint4*)&Ks[r * KP + lc + 16] = *(const uint4*)&Kt[r * HDIM + (lc + 16) * 2];
            *(uint4*)&Vs[r * KP + lc]      = *(const uint4*)&Vt[r * HDIM + lc * 2];
            *(uint4*)&Vs[r * KP + lc + 16] = *(const uint4*)&Vt[r * HDIM + (lc + 16) * 2];
        }
        __syncthreads();

#pragma unroll
        for (int c2 = 0; c2 < 2; c2++) {
            const int colb = jt * 128 + c2 * 64;
            if (colb > wr0 + 15) break;     // chunks ascend; rest also masked
            const uint32_t kbase = ks_base + (uint32_t)(c2 * 64 * KP * 4);
            const uint32_t vbase = vs_base + (uint32_t)(c2 * 64 * KP * 4);

            float c[8][4];
#pragma unroll
            for (int nf = 0; nf < 8; nf++)
#pragma unroll
                for (int r = 0; r < 4; r++) c[nf][r] = 0.0f;

#pragma unroll
            for (int kb = 0; kb < 4; kb++) {
#pragma unroll
                for (int np = 0; np < 4; np++) {
                    const int krow = np * 16 + (quad >> 1) * 8 + idx8;
                    const int kwrd = kb * 8 + (quad & 1) * 4;
                    uint32_t r0, r1, r2, r3;
                    ldmatrix_x4(r0, r1, r2, r3, kbase + (uint32_t)((krow * KP + kwrd) * 4));
                    mma_f16(c[2 * np],     qa[kb][0], qa[kb][1], qa[kb][2], qa[kb][3], r0, r1);
                    mma_f16(c[2 * np + 1], qa[kb][0], qa[kb][1], qa[kb][2], qa[kb][3], r2, r3);
                }
            }

            const bool diag = (colb + 63 > wr0);
            if (diag) {
#pragma unroll
                for (int nf = 0; nf < 8; nf++) {
#pragma unroll
                    for (int r = 0; r < 4; r++) {
                        const int col = colb + nf * 8 + 2 * tq + (r & 1);
                        const int row = wr0 + g + ((r >= 2) ? 8 : 0);
                        if (col > row) c[nf][r] = -1e30f;
                    }
                }
            }

            float tm0 = -1e30f, tm1 = -1e30f;
#pragma unroll
            for (int nf = 0; nf < 8; nf++) {
                tm0 = fmaxf(tm0, fmaxf(c[nf][0], c[nf][1]));
                tm1 = fmaxf(tm1, fmaxf(c[nf][2], c[nf][3]));
            }
#pragma unroll
            for (int off = 1; off <= 2; off <<= 1) {
                tm0 = fmaxf(tm0, __shfl_xor_sync(0xffffffffu, tm0, off));
                tm1 = fmaxf(tm1, __shfl_xor_sync(0xffffffffu, tm1, off));
            }
            const float nm0 = fmaxf(m0, tm0);
            const float nm1 = fmaxf(m1, tm1);
            const float al0 = ex2(m0 - nm0);
            const float al1 = ex2(m1 - nm1);
            float rs0 = 0.0f, rs1 = 0.0f;
#pragma unroll
            for (int nf = 0; nf < 8; nf++) {
                c[nf][0] = ex2(c[nf][0] - nm0);
                c[nf][1] = ex2(c[nf][1] - nm0);
                c[nf][2] = ex2(c[nf][2] - nm1);
                c[nf][3] = ex2(c[nf][3] - nm1);
                rs0 += c[nf][0] + c[nf][1];
                rs1 += c[nf][2] + c[nf][3];
            }
#pragma unroll
            for (int off = 1; off <= 2; off <<= 1) {
                rs0 += __shfl_xor_sync(0xffffffffu, rs0, off);
                rs1 += __shfl_xor_sync(0xffffffffu, rs1, off);
            }
            l0 = l0 * al0 + rs0;  m0 = nm0;
            l1 = l1 * al1 + rs1;  m1 = nm1;
#pragma unroll
            for (int nf = 0; nf < 8; nf++) {
                o[nf][0] *= al0;  o[nf][1] *= al0;
                o[nf][2] *= al1;  o[nf][3] *= al1;
            }

#pragma unroll
            for (int kb2 = 0; kb2 < 4; kb2++) {
                const uint32_t a0 = pack_f16(c[2 * kb2][0],     c[2 * kb2][1]);
                const uint32_t a1 = pack_f16(c[2 * kb2][2],     c[2 * kb2][3]);
                const uint32_t a2 = pack_f16(c[2 * kb2 + 1][0], c[2 * kb2 + 1][1]);
                const uint32_t a3 = pack_f16(c[2 * kb2 + 1][2], c[2 * kb2 + 1][3]);
#pragma unroll
                for (int np = 0; np < 4; np++) {
                    const int vrow = kb2 * 16 + (quad & 1) * 8 + idx8;
                    const int vwrd = np * 8 + (quad >> 1) * 4;
                    uint32_t r0, r1, r2, r3;
                    ldmatrix_x4_trans(r0, r1, r2, r3,
                                      vbase + (uint32_t)((vrow * KP + vwrd) * 4));
                    mma_f16(o[2 * np],     a0, a1, a2, a3, r0, r1);
                    mma_f16(o[2 * np + 1], a0, a1, a2, a3, r2, r3);
                }
            }
        }
    }

    // ---- normalize & store ctx as fp16 into g_Xh ----
    const float inv0 = 1.0f / l0;
    const float inv1 = 1.0f / l1;
    const size_t r0off = ((size_t)(b * SEQ) + wr0 + g) * D_MODEL + h * HDIM;
    const size_t r1off = ((size_t)(b * SEQ) + wr0 + g + 8) * D_MODEL + h * HDIM;
#pragma unroll
    for (int nf = 0; nf < 8; nf++) {
        const int col = nf * 8 + 2 * tq;
        __half2 p0 = __floats2half2_rn(o[nf][0] * inv0, o[nf][1] * inv0);
        __half2 p1 = __floats2half2_rn(o[nf][2] * inv1, o[nf][3] * inv1);
        *(__half2*)&g_Xh[r0off + col] = p0;
        *(__half2*)&g_Xh[r1off + col] = p1;
    }
}

// =================================================================================
// Launch
// =================================================================================
extern "C" void kernel_launch(void* const* d_in, const int* in_sizes, int n_in,
                              void* d_out, int out_size)
{
    const float* x  = (const float*)d_in[0];
    const float* Wq = (const float*)d_in[1];
    const float* Wk = (const float*)d_in[2];
    const float* Wv = (const float*)d_in[3];
    const float* Wo = (const float*)d_in[4];
    float* out = (float*)d_out;

    cudaFuncSetAttribute(f16_gemm<1>, cudaFuncAttributeMaxDynamicSharedMemorySize, GSMEM);
    cudaFuncSetAttribute(f16_gemm<0>, cudaFuncAttributeMaxDynamicSharedMemorySize, GSMEM);

    conv_x_kernel<<<NROWS * D_MODEL / 1024, 256>>>(x);
    conv_w_kernel<<<dim3(D_MODEL * D_MODEL / 1024, 1, 4), 256>>>(Wq, Wk, Wv, Wo);

    f16_gemm<1><<<dim3(D_MODEL / 128, NROWS / 256, 3), 512, GSMEM>>>(nullptr);

    attn_mma_kernel<<<dim3(SEQ / QTILE, NHEADS, BATCH), 256>>>();

    f16_gemm<0><<<dim3(D_MODEL / 128, NROWS / 256, 1), 512, GSMEM>>>(out);
}

// round 16
// speedup vs baseline: 1.1128x; 1.1128x over previous
#include <cuda_runtime.h>
#include <cuda_fp16.h>
#include <cstdint>

#define D_MODEL 1024
#define NHEADS  16
#define HDIM    64
#define BATCH   2
#define SEQ     2048
#define NROWS   (BATCH * SEQ)   // 4096
#define QTILE   128

// 0.125 * log2(e): folded into Wq so attention scores are in log2 units pre-scaled
#define QSCALE 0.18033688011112042f

// ---------------- scratch (static device globals; no allocations) ----------------
__device__ __half g_Qh[BATCH * NHEADS * SEQ * HDIM];   // [B,H,S,Dh] fp16
__device__ __half g_Kh[BATCH * NHEADS * SEQ * HDIM];
__device__ __half g_Vh[BATCH * NHEADS * SEQ * HDIM];
__device__ __half g_Xh[NROWS * D_MODEL];               // fp16: x, then ctx
__device__ __half g_Wh[4 * D_MODEL * D_MODEL];         // fp16 W [z][k][n] (Wq pre-scaled)

// ---------------- ptx helpers (sm_80-class only; NO tcgen05 on this target) ------
__device__ __forceinline__ void cp16(uint32_t smem, const void* gmem) {
    asm volatile("cp.async.cg.shared.global [%0], [%1], 16;" :: "r"(smem), "l"(gmem));
}
#define CP_COMMIT() asm volatile("cp.async.commit_group;" ::: "memory")
template <int N>
__device__ __forceinline__ void cp_wait() {
    asm volatile("cp.async.wait_group %0;" :: "n"(N) : "memory");
}
__device__ __forceinline__ float ex2(float x) {
    float y;
    asm("ex2.approx.f32 %0, %1;" : "=f"(y) : "f"(x));
    return y;
}
__device__ __forceinline__ void ldmatrix_x4(uint32_t& r0, uint32_t& r1,
                                            uint32_t& r2, uint32_t& r3, uint32_t addr) {
    asm volatile("ldmatrix.sync.aligned.m8n8.x4.shared.b16 {%0,%1,%2,%3}, [%4];"
                 : "=r"(r0), "=r"(r1), "=r"(r2), "=r"(r3) : "r"(addr));
}
__device__ __forceinline__ void ldmatrix_x4_trans(uint32_t& r0, uint32_t& r1,
                                                  uint32_t& r2, uint32_t& r3, uint32_t addr) {
    asm volatile("ldmatrix.sync.aligned.m8n8.x4.trans.shared.b16 {%0,%1,%2,%3}, [%4];"
                 : "=r"(r0), "=r"(r1), "=r"(r2), "=r"(r3) : "r"(addr));
}
__device__ __forceinline__ void mma_f16(float* c,
    uint32_t a0, uint32_t a1, uint32_t a2, uint32_t a3, uint32_t b0, uint32_t b1)
{
    asm volatile(
        "mma.sync.aligned.m16n8k16.row.col.f32.f16.f16.f32 "
        "{%0,%1,%2,%3}, {%4,%5,%6,%7}, {%8,%9}, {%0,%1,%2,%3};\n"
        : "+f"(c[0]), "+f"(c[1]), "+f"(c[2]), "+f"(c[3])
        : "r"(a0), "r"(a1), "r"(a2), "r"(a3), "r"(b0), "r"(b1));
}
__device__ __forceinline__ uint32_t pack_f16(float x0, float x1) {
    __half2 h = __floats2half2_rn(x0, x1);
    return *(uint32_t*)&h;
}

// =================================================================================
// Pre-pass: fp16 conversions. Wq is pre-scaled by QSCALE (attention scale fold).
// =================================================================================
__global__ __launch_bounds__(256) void conv_x_kernel(const float* __restrict__ src)
{
    const size_t i = ((size_t)blockIdx.x * 256 + threadIdx.x) * 4;
    float4 v = *(const float4*)(src + i);
    __half2 p0 = __floats2half2_rn(v.x, v.y);
    __half2 p1 = __floats2half2_rn(v.z, v.w);
    *(uint2*)(g_Xh + i) = make_uint2(*(uint32_t*)&p0, *(uint32_t*)&p1);
}
__global__ __launch_bounds__(256) void conv_w_kernel(
    const float* __restrict__ W0, const float* __restrict__ W1,
    const float* __restrict__ W2, const float* __restrict__ W3)
{
    const float* W = (blockIdx.z == 0) ? W0 : (blockIdx.z == 1) ? W1
                   : (blockIdx.z == 2) ? W2 : W3;
    const float s = (blockIdx.z == 0) ? QSCALE : 1.0f;
    const size_t o = (size_t)blockIdx.z * D_MODEL * D_MODEL;
    const size_t i = ((size_t)blockIdx.x * 256 + threadIdx.x) * 4;
    float4 v = *(const float4*)(W + i);
    __half2 p0 = __floats2half2_rn(v.x * s, v.y * s);
    __half2 p1 = __floats2half2_rn(v.z * s, v.w * s);
    *(uint2*)(g_Wh + o + i) = make_uint2(*(uint32_t*)&p0, *(uint32_t*)&p1);
}

// =================================================================================
// fp16 1-pass GEMM (verified Round-13 tiles): 3-stage cp.async pipeline, BK=32,
// block 128x128, 256 threads = 8 warps (2x4), warp tile 64x32.
// A smem [m][k] pitch 80B (ldmatrix.x4); B smem [k][n] pitch 272B (ldmatrix.trans).
// QKV=1: A=g_Xh(x), B=g_Wh[z], out -> fp16 g_Qh/g_Kh/g_Vh [B,H,S,Dh].
// QKV=0: A=g_Xh(ctx), B=g_Wh[3](Wo), out -> fp32 row-major Cout.
// =================================================================================
#define STG_A 0
#define STG_B 10240
#define STG_SZ 18944
#define GSMEM (3 * STG_SZ)   // 56832

template <int QKV>
__global__ __launch_bounds__(256, 2) void f16_gemm(float* __restrict__ Cout)
{
    extern __shared__ uint8_t smem[];
    const uint32_t sb = (uint32_t)__cvta_generic_to_shared(smem);
    const int t = threadIdx.x, lane = t & 31, wid = t >> 5;
    const int g = lane >> 2, tq = lane & 3, quad = lane >> 3, idx8 = lane & 7;
    const int wm = (wid & 1) * 64, wn = (wid >> 1) * 32;
    const int m0 = blockIdx.y * 128, n0 = blockIdx.x * 128;
    const int z  = QKV ? (int)blockIdx.z : 3;

    const __half* A  = g_Xh;
    const __half* Wp = g_Wh + (size_t)z * D_MODEL * D_MODEL;

    float acc[4][4][4];
#pragma unroll
    for (int mf = 0; mf < 4; mf++)
#pragma unroll
        for (int nf = 0; nf < 4; nf++)
#pragma unroll
            for (int r = 0; r < 4; r++) acc[mf][nf][r] = 0.0f;

    auto load_stage = [&](int buf, int ks) {
        const uint32_t base = sb + buf * STG_SZ;
#pragma unroll
        for (int half = 0; half < 2; half++) {
            const int row = (t >> 2) + half * 64;
            cp16(base + STG_A + row * 80 + (t & 3) * 16,
                 A + (size_t)(m0 + row) * D_MODEL + ks + (t & 3) * 8);
        }
#pragma unroll
        for (int half = 0; half < 2; half++) {
            const int row = (t >> 4) + half * 16;
            cp16(base + STG_B + row * 272 + (t & 15) * 16,
                 Wp + (size_t)(ks + row) * D_MODEL + n0 + (t & 15) * 8);
        }
        CP_COMMIT();
    };

    load_stage(0, 0);
    load_stage(1, 32);
    load_stage(2, 64);
    int ks = 96;
    int buf = 0;

    constexpr int NIT = D_MODEL / 32;   // 32
    for (int it = 0; it < NIT; ++it) {
        if (it < NIT - 2)       cp_wait<2>();
        else if (it == NIT - 2) cp_wait<1>();
        else                    cp_wait<0>();
        __syncthreads();

        const uint32_t ab = sb + buf * STG_SZ;
        const uint32_t aA = ab + STG_A, aB = ab + STG_B;

#pragma unroll
        for (int kb = 0; kb < 2; kb++) {
            uint32_t af[4][4], bf[4][2];
#pragma unroll
            for (int mf = 0; mf < 4; mf++) {
                const uint32_t off =
                    (uint32_t)((wm + mf * 16 + (lane & 15)) * 80 +
                               (kb * 8 + (lane >> 4) * 4) * 4);
                ldmatrix_x4(af[mf][0], af[mf][1], af[mf][2], af[mf][3], aA + off);
            }
#pragma unroll
            for (int np = 0; np < 2; np++) {
                const uint32_t boff =
                    (uint32_t)((kb * 16 + (quad & 1) * 8 + idx8) * 272 +
                               (wn / 2 + np * 8 + (quad >> 1) * 4) * 4);
                uint32_t r0, r1, r2, r3;
                ldmatrix_x4_trans(r0, r1, r2, r3, aB + boff);
                bf[2 * np][0] = r0; bf[2 * np][1] = r1;
                bf[2 * np + 1][0] = r2; bf[2 * np + 1][1] = r3;
            }
#pragma unroll
            for (int mf = 0; mf < 4; mf++)
#pragma unroll
                for (int nf = 0; nf < 4; nf++)
                    mma_f16(acc[mf][nf], af[mf][0], af[mf][1], af[mf][2], af[mf][3],
                            bf[nf][0], bf[nf][1]);
        }
        __syncthreads();
        if (it + 3 < NIT) {
            load_stage(buf, ks);
            ks += 32;
        }
        buf = (buf == 2) ? 0 : buf + 1;
    }

    // epilogue (verified layout): c0=(g,2tq) c1=(g,2tq+1) c2=(g+8,2tq) c3=(g+8,2tq+1)
#pragma unroll
    for (int mf = 0; mf < 4; mf++) {
#pragma unroll
        for (int nf = 0; nf < 4; nf++) {
            const int n = n0 + wn + nf * 8 + 2 * tq;
#pragma unroll
            for (int half = 0; half < 2; half++) {
                const int m = m0 + wm + mf * 16 + g + half * 8;
                const float c0 = acc[mf][nf][half * 2 + 0];
                const float c1 = acc[mf][nf][half * 2 + 1];
                if (QKV) {
                    const int b  = m >> 11;
                    const int s  = m & (SEQ - 1);
                    const int h  = n >> 6;
                    const int dd = n & (HDIM - 1);
                    __half2 hv = __floats2half2_rn(c0, c1);
                    __half* dst = (z == 0) ? g_Qh : (z == 1) ? g_Kh : g_Vh;
                    *(__half2*)&dst[(((size_t)(b * NHEADS + h)) * SEQ + s) * HDIM + dd] = hv;
                } else {
                    *(float2*)&Cout[(size_t)m * D_MODEL + n] = make_float2(c0, c1);
                }
            }
        }
    }
}

// =================================================================================
// fp16 tensor-core causal flash attention (verified Round-13 body, KV tile 64).
// Scores in log2 units (Wq pre-scaled), exp = EX2. Chain trims: per-lane partial
// l (quad-reduced once at end) and conditional o-rescale. Ctx fp16 -> g_Xh.
// =================================================================================
__global__ __launch_bounds__(256, 2) void attn_mma_kernel()
{
    constexpr int KP = 36;
    __shared__ __align__(16) uint32_t Ks[64 * KP];
    __shared__ __align__(16) uint32_t Vs[64 * KP];

    const int t    = threadIdx.x;
    const int lane = t & 31;
    const int wid  = t >> 5;
    const int g    = lane >> 2;
    const int tq   = lane & 3;
    const int quad = lane >> 3;
    const int idx8 = lane & 7;

    const int qt = (int)gridDim.x - 1 - (int)blockIdx.x;
    const int h  = blockIdx.y;
    const int b  = blockIdx.z;
    const int bh = b * NHEADS + h;
    const __half* Qb = g_Qh + (size_t)bh * SEQ * HDIM;
    const __half* Kb = g_Kh + (size_t)bh * SEQ * HDIM;
    const __half* Vb = g_Vh + (size_t)bh * SEQ * HDIM;
    const int q0  = qt * QTILE;
    const int wr0 = q0 + wid * 16;

    uint32_t qa[4][4];
#pragma unroll
    for (int kb = 0; kb < 4; kb++) {
        const int col = kb * 16 + 2 * tq;
        qa[kb][0] = *(const uint32_t*)&Qb[(size_t)(wr0 + g) * HDIM + col];
        qa[kb][1] = *(const uint32_t*)&Qb[(size_t)(wr0 + g + 8) * HDIM + col];
        qa[kb][2] = *(const uint32_t*)&Qb[(size_t)(wr0 + g) * HDIM + col + 8];
        qa[kb][3] = *(const uint32_t*)&Qb[(size_t)(wr0 + g + 8) * HDIM + col + 8];
    }

    float m0 = -1e30f, m1 = -1e30f, l0 = 0.0f, l1 = 0.0f;   // l: per-lane partial
    float o[8][4];
#pragma unroll
    for (int nf = 0; nf < 8; nf++)
#pragma unroll
        for (int r = 0; r < 4; r++) o[nf][r] = 0.0f;

    const uint32_t ks_base = (uint32_t)__cvta_generic_to_shared(Ks);
    const uint32_t vs_base = (uint32_t)__cvta_generic_to_shared(Vs);

    const int lr = t >> 2;
    const int lc = (t & 3) * 4;

    const int njt = (q0 + QTILE) / 64;
    for (int jt = 0; jt < njt; jt++) {
        __syncthreads();
        const __half* Kt = Kb + (size_t)jt * 64 * HDIM;
        const __half* Vt = Vb + (size_t)jt * 64 * HDIM;
        *(uint4*)&Ks[lr * KP + lc]      = *(const uint4*)&Kt[lr * HDIM + lc * 2];
        *(uint4*)&Ks[lr * KP + lc + 16] = *(const uint4*)&Kt[lr * HDIM + (lc + 16) * 2];
        *(uint4*)&Vs[lr * KP + lc]      = *(const uint4*)&Vt[lr * HDIM + lc * 2];
        *(uint4*)&Vs[lr * KP + lc + 16] = *(const uint4*)&Vt[lr * HDIM + (lc + 16) * 2];
        __syncthreads();

        if (jt * 64 > wr0 + 15) continue;

        float c[8][4];
#pragma unroll
        for (int nf = 0; nf < 8; nf++)
#pragma unroll
            for (int r = 0; r < 4; r++) c[nf][r] = 0.0f;

#pragma unroll
        for (int kb = 0; kb < 4; kb++) {
#pragma unroll
            for (int np = 0; np < 4; np++) {
                const int krow = np * 16 + (quad >> 1) * 8 + idx8;
                const int kwrd = kb * 8 + (quad & 1) * 4;
                uint32_t r0, r1, r2, r3;
                ldmatrix_x4(r0, r1, r2, r3, ks_base + (uint32_t)((krow * KP + kwrd) * 4));
                mma_f16(c[2 * np],     qa[kb][0], qa[kb][1], qa[kb][2], qa[kb][3], r0, r1);
                mma_f16(c[2 * np + 1], qa[kb][0], qa[kb][1], qa[kb][2], qa[kb][3], r2, r3);
            }
        }

        // causal mask (scores pre-scaled via Wq fold); only diagonal tiles mask
        const bool diag = (jt * 64 + 63 > wr0);
        if (diag) {
#pragma unroll
            for (int nf = 0; nf < 8; nf++) {
#pragma unroll
                for (int r = 0; r < 4; r++) {
                    const int col = jt * 64 + nf * 8 + 2 * tq + (r & 1);
                    const int row = wr0 + g + ((r >= 2) ? 8 : 0);
                    if (col > row) c[nf][r] = -1e30f;
                }
            }
        }

        // online softmax (log2 domain). Max reduced across quad; l stays per-lane.
        float tm0 = -1e30f, tm1 = -1e30f;
#pragma unroll
        for (int nf = 0; nf < 8; nf++) {
            tm0 = fmaxf(tm0, fmaxf(c[nf][0], c[nf][1]));
            tm1 = fmaxf(tm1, fmaxf(c[nf][2], c[nf][3]));
        }
#pragma unroll
        for (int off = 1; off <= 2; off <<= 1) {
            tm0 = fmaxf(tm0, __shfl_xor_sync(0xffffffffu, tm0, off));
            tm1 = fmaxf(tm1, __shfl_xor_sync(0xffffffffu, tm1, off));
        }
        const float nm0 = fmaxf(m0, tm0);
        const float nm1 = fmaxf(m1, tm1);
        const float al0 = ex2(m0 - nm0);
        const float al1 = ex2(m1 - nm1);
        float rs0 = 0.0f, rs1 = 0.0f;
#pragma unroll
        for (int nf = 0; nf < 8; nf++) {
            c[nf][0] = ex2(c[nf][0] - nm0);
            c[nf][1] = ex2(c[nf][1] - nm0);
            c[nf][2] = ex2(c[nf][2] - nm1);
            c[nf][3] = ex2(c[nf][3] - nm1);
            rs0 += c[nf][0] + c[nf][1];
            rs1 += c[nf][2] + c[nf][3];
        }
        l0 = l0 * al0 + rs0;  m0 = nm0;
        l1 = l1 * al1 + rs1;  m1 = nm1;
        if (al0 != 1.0f || al1 != 1.0f) {
#pragma unroll
            for (int nf = 0; nf < 8; nf++) {
                o[nf][0] *= al0;  o[nf][1] *= al0;
                o[nf][2] *= al1;  o[nf][3] *= al1;
            }
        }

#pragma unroll
        for (int kb2 = 0; kb2 < 4; kb2++) {
            const uint32_t a0 = pack_f16(c[2 * kb2][0],     c[2 * kb2][1]);
            const uint32_t a1 = pack_f16(c[2 * kb2][2],     c[2 * kb2][3]);
            const uint32_t a2 = pack_f16(c[2 * kb2 + 1][0], c[2 * kb2 + 1][1]);
            const uint32_t a3 = pack_f16(c[2 * kb2 + 1][2], c[2 * kb2 + 1][3]);
#pragma unroll
            for (int np = 0; np < 4; np++) {
                const int vrow = kb2 * 16 + (quad & 1) * 8 + idx8;
                const int vwrd = np * 8 + (quad >> 1) * 4;
                uint32_t r0, r1, r2, r3;
                ldmatrix_x4_trans(r0, r1, r2, r3, vs_base + (uint32_t)((vrow * KP + vwrd) * 4));
                mma_f16(o[2 * np],     a0, a1, a2, a3, r0, r1);
                mma_f16(o[2 * np + 1], a0, a1, a2, a3, r2, r3);
            }
        }
    }

    // final l reduction across the quad (deferred from the per-chunk loop)
#pragma unroll
    for (int off = 1; off <= 2; off <<= 1) {
        l0 += __shfl_xor_sync(0xffffffffu, l0, off);
        l1 += __shfl_xor_sync(0xffffffffu, l1, off);
    }

    // ---- normalize & store ctx as fp16 into g_Xh ----
    const float inv0 = 1.0f / l0;
    const float inv1 = 1.0f / l1;
    const size_t r0off = ((size_t)(b * SEQ) + wr0 + g) * D_MODEL + h * HDIM;
    const size_t r1off = ((size_t)(b * SEQ) + wr0 + g + 8) * D_MODEL + h * HDIM;
#pragma unroll
    for (int nf = 0; nf < 8; nf++) {
        const int col = nf * 8 + 2 * tq;
        __half2 p0 = __floats2half2_rn(o[nf][0] * inv0, o[nf][1] * inv0);
        __half2 p1 = __floats2half2_rn(o[nf][2] * inv1, o[nf][3] * inv1);
        *(__half2*)&g_Xh[r0off + col] = p0;
        *(__half2*)&g_Xh[r1off + col] = p1;
    }
}

// =================================================================================
// Launch
// =================================================================================
extern "C" void kernel_launch(void* const* d_in, const int* in_sizes, int n_in,
                              void* d_out, int out_size)
{
    const float* x  = (const float*)d_in[0];
    const float* Wq = (const float*)d_in[1];
    const float* Wk = (const float*)d_in[2];
    const float* Wv = (const float*)d_in[3];
    const float* Wo = (const float*)d_in[4];
    float* out = (float*)d_out;

    cudaFuncSetAttribute(f16_gemm<1>, cudaFuncAttributeMaxDynamicSharedMemorySize, GSMEM);
    cudaFuncSetAttribute(f16_gemm<0>, cudaFuncAttributeMaxDynamicSharedMemorySize, GSMEM);

    conv_x_kernel<<<NROWS * D_MODEL / 1024, 256>>>(x);
    conv_w_kernel<<<dim3(D_MODEL * D_MODEL / 1024, 1, 4), 256>>>(Wq, Wk, Wv, Wo);

    f16_gemm<1><<<dim3(D_MODEL / 128, NROWS / 128, 3), 256, GSMEM>>>(nullptr);

    attn_mma_kernel<<<dim3(SEQ / QTILE, NHEADS, BATCH), 256>>>();

    f16_gemm<0><<<dim3(D_MODEL / 128, NROWS / 128, 1), 256, GSMEM>>>(out);
}